// round 16
// baseline (speedup 1.0000x reference)
#include <cuda_runtime.h>

// Problem: volume [40,40,40,32] f32, M [32,32], P [32,32] -> Nk [59319,32]
//   b = (k1*39 + k2)*39 + k3
//   Nk[b,i] = sum_j x[b,j] * P[i,j] * cos(k1*a_ij) * cos(k2*a_ij) * cos(k3*a_ij)
//   a_ij = 2pi/(i*32+j+2),  x = (2x2x2 mean pool) @ M^T
//
// R16 = R10 monolith (register-resident Chebyshev march over k3, WPB=11,
// single wave) with the matvec (phase C) reworked to f32x2: two k3 rows
// packed per lane-pair, M staged as duplicated-pair table MT2 -> matvec
// FFMA warp-instructions halved. March (phases D/E) unchanged.
#define NP    39
#define NPAIR (39*39)     // 1521
#define WPB   11          // pairs (warps) per block
#define TPB   (WPB*32)    // 352
#define PI2F  6.2831853071795864769f

typedef unsigned long long ull;

__device__ float g_tab[39 * 1024];   // tab[k][j*32+i] = cos(k*2pi/(i*32+j+2))

// ---- f32x2 packed math (sm_103a) ------------------------------------------
__device__ __forceinline__ ull f2_mul(ull a, ull b) {
    ull d; asm("mul.rn.f32x2 %0, %1, %2;" : "=l"(d) : "l"(a), "l"(b)); return d;
}
__device__ __forceinline__ ull f2_fma(ull a, ull b, ull c) {
    ull d; asm("fma.rn.f32x2 %0, %1, %2, %3;" : "=l"(d) : "l"(a), "l"(b), "l"(c)); return d;
}
__device__ __forceinline__ ull f2_add(ull a, ull b) {
    ull d; asm("add.rn.f32x2 %0, %1, %2;" : "=l"(d) : "l"(a), "l"(b)); return d;
}
__device__ __forceinline__ ull f2_pack2(float lo, float hi) {
    ull d; asm("mov.b64 %0, {%1, %2};" : "=l"(d) : "f"(lo), "f"(hi)); return d;
}
__device__ __forceinline__ float2 f2_unpack(ull v) {
    float2 r; asm("mov.b64 {%0, %1}, %2;" : "=f"(r.x), "=f"(r.y) : "l"(v)); return r;
}

// ---------------------------------------------------------------------------
// Kernel 0: cos table via Chebyshev recurrence. grid 4 x 256.
// ---------------------------------------------------------------------------
__global__ void k_pre() {
    int t = blockIdx.x * 256 + threadIdx.x;   // t = j*32 + i
    int i = t & 31, j = t >> 5;
    float a  = PI2F / (float)(i * 32 + j + 2);
    float c1 = cosf(a);
    float twoc = 2.0f * c1;
    float cm2 = 1.0f, cm1 = c1;
    g_tab[t]        = 1.0f;
    g_tab[1024 + t] = c1;
#pragma unroll
    for (int k = 2; k < 39; k++) {
        float ck = twoc * cm1 - cm2;
        g_tab[k * 1024 + t] = ck;
        cm2 = cm1; cm1 = ck;
    }
}

// ---------------------------------------------------------------------------
// Main kernel: grid 139 x 352 threads, 129.1 KB dynamic smem.
// ---------------------------------------------------------------------------
// smem float offsets (16B-aligned where vector-accessed):
#define S_PT    0        // 1056   P^T padded [j*33 + i]
#define S_MT2   1056     // 2048   MT2[l*32 + j] as f32x2 pair (M[j][l], M[j][l])
#define S_POOL  3104     // 11*1404 = 15444  pooled[lp][k3*36 + ch]
#define S_X     18548    // 11*1248 = 13728  x'[lp][k3*32 + j] (sign folded)
#define SM_FLOATS 32276

__global__ void __launch_bounds__(TPB) k_main(
    const float* __restrict__ vol, const float* __restrict__ Mw,
    const float* __restrict__ P, float* __restrict__ out)
{
    extern __shared__ float sm[];
    const int tid  = threadIdx.x;
    const int lane = tid & 31;
    const int wid  = tid >> 5;
    const int p0   = blockIdx.x * WPB;
    const int pair = p0 + wid;
    const bool valid = (pair < NPAIR);

    // -------- Phase A: stage P^T (padded) and MT2 (duplicated-pair M^T) ----
    for (int g = tid; g < 1024; g += TPB) {
        sm[S_PT + (g & 31) * 33 + (g >> 5)] = P[g];           // PT[j][i] = P[i][j]
        float m = Mw[(g & 31) * 32 + (g >> 5)];               // g = l*32+j -> M[j][l]
        sm[S_MT2 + g * 2]     = m;
        sm[S_MT2 + g * 2 + 1] = m;
    }
    __syncthreads();

    // -------- Phase B: pooling (per-pair, 8 independent LDG.128) --------
    for (int job = tid; job < WPB * 312; job += TPB) {
        int lp  = job / 312;
        int rem = job - lp * 312;
        int k3  = rem >> 3;
        int cq  = rem & 7;
        int gp  = p0 + lp;
        if (gp >= NPAIR) continue;
        int kk1 = gp / 39, kk2 = gp - kk1 * 39;
        const float* base = vol + (((kk1 * 40) + kk2) * 40 + k3) * 32 + cq * 4;
        float4 s = make_float4(0.f, 0.f, 0.f, 0.f);
#pragma unroll
        for (int dd = 0; dd < 2; dd++)
#pragma unroll
            for (int hh = 0; hh < 2; hh++)
#pragma unroll
                for (int ww = 0; ww < 2; ww++) {
                    float4 v = *(const float4*)(base + dd * 51200 + hh * 1280 + ww * 32);
                    s.x += v.x; s.y += v.y; s.z += v.z; s.w += v.w;
                }
        s.x *= 0.125f; s.y *= 0.125f; s.z *= 0.125f; s.w *= 0.125f;
        *(float4*)&sm[S_POOL + lp * 1404 + k3 * 36 + cq * 4] = s;
    }
    __syncthreads();

    // -------- Phase C: f32x2 matvec, 2 k3 rows per lane-pair --------
    // job = (lp, kp, jq): 11 * 20 * 8 = 1760 jobs = 5 exact rounds of 352.
    // x'[k3][j] = s_k3 * sum_l pooled[k3][l] * M[j][l]
    for (int job = tid; job < WPB * 160; job += TPB) {
        int lp  = job / 160;
        int rem = job - lp * 160;
        int kp  = rem >> 3;
        int jq  = rem & 7;
        int k3a = kp * 2;
        int k3b = (k3a + 1 > 38) ? 38 : k3a + 1;
        int gp  = p0 + lp;
        const float* pA = &sm[S_POOL + lp * 1404 + k3a * 36];
        const float* pB = &sm[S_POOL + lp * 1404 + k3b * 36];
        const ulonglong2* mt2 = (const ulonglong2*)(sm + S_MT2);
        ull a0 = 0, a1 = 0, a2 = 0, a3 = 0;
        if (gp < NPAIR) {
#pragma unroll
            for (int l = 0; l < 32; l++) {
                ull pp = f2_pack2(pA[l], pB[l]);              // (pooled_a, pooled_b)
                ulonglong2 mA = mt2[l * 16 + jq * 2];         // (m,m) pairs, j = jq*4..+1
                ulonglong2 mB = mt2[l * 16 + jq * 2 + 1];     // j = jq*4+2..+3
                a0 = f2_fma(pp, mA.x, a0);
                a1 = f2_fma(pp, mA.y, a1);
                a2 = f2_fma(pp, mB.x, a2);
                a3 = f2_fma(pp, mB.y, a3);
            }
        }
        float sA = (k3a & 2) ? -1.0f : 1.0f;                  // s_k: +,+,-,-
        float sB = (k3b & 2) ? -1.0f : 1.0f;
        ull ss = f2_pack2(sA, sB);
        float2 f0 = f2_unpack(f2_mul(a0, ss));
        float2 f1 = f2_unpack(f2_mul(a1, ss));
        float2 f2v = f2_unpack(f2_mul(a2, ss));
        float2 f3 = f2_unpack(f2_mul(a3, ss));
        *(float4*)&sm[S_X + lp * 1248 + k3a * 32 + jq * 4] =
            make_float4(f0.x, f1.x, f2v.x, f3.x);
        *(float4*)&sm[S_X + lp * 1248 + k3b * 32 + jq * 4] =
            make_float4(f0.y, f1.y, f2v.y, f3.y);
    }
    __syncthreads();

    if (!valid) return;                                       // no syncs after this

    // -------- Phase D: per-warp seeds (PT smem + g_tab rows) --------
    const int k1 = pair / 39, k2 = pair - (pair / 39) * 39;
    const float* t1r = g_tab + k1 * 1024;
    const float* t2r = g_tab + k2 * 1024;
    const float* cr  = g_tab + 1024;                          // k=1 row: cos(a)

    ull w0[16], w1[16], p2[16], m2[16];
#pragma unroll
    for (int jp = 0; jp < 16; jp++) {
        int t0 = (2 * jp) * 32 + lane, t1 = t0 + 32;
        float pa = sm[S_PT + (2 * jp) * 33 + lane];
        float pb = sm[S_PT + (2 * jp + 1) * 33 + lane];
        float a0 = pa * t1r[t0] * t2r[t0];                    // A[i, 2jp]
        float a1 = pb * t1r[t1] * t2r[t1];                    // A[i, 2jp+1]
        float c0 = cr[t0], c1 = cr[t1];
        w0[jp] = f2_pack2(a0, a1);                            // w_0 = A
        w1[jp] = f2_pack2(a0 * c0, a1 * c1);                  // w_1 = A*c
        p2[jp] = f2_pack2(2.0f * c0, 2.0f * c1);              // +2c
        m2[jp] = f2_pack2(-2.0f * c0, -2.0f * c1);            // -2c
    }

    // -------- Phase E: march k3; x-row LDS hoisted ahead of recurrence ----
    const ulonglong2* xq = (const ulonglong2*)(sm + S_X + wid * 1248);
    float* outp = out + pair * (NP * 32) + lane;
    ulonglong2 xb[8];

#define XLOAD(K3) do { _Pragma("unroll")                                  \
    for (int q = 0; q < 8; q++) xb[q] = xq[(K3) * 8 + q]; } while (0)

#define DOT_TAIL(W, K3) do {                                              \
    ull a0 = 0, a1 = 0, a2 = 0, a3 = 0;                                   \
    _Pragma("unroll")                                                     \
    for (int q = 0; q < 8; q += 2) {                                      \
        a0 = f2_fma(W[2*q + 0], xb[q].x,     a0);                         \
        a1 = f2_fma(W[2*q + 1], xb[q].y,     a1);                         \
        a2 = f2_fma(W[2*q + 2], xb[q + 1].x, a2);                         \
        a3 = f2_fma(W[2*q + 3], xb[q + 1].y, a3);                         \
    }                                                                     \
    float2 fr = f2_unpack(f2_add(f2_add(a0, a1), f2_add(a2, a3)));        \
    outp[(K3) * 32] = fr.x + fr.y;                                        \
} while (0)

    XLOAD(0); DOT_TAIL(w0, 0);
    XLOAD(1); DOT_TAIL(w1, 1);

#pragma unroll 1
    for (int k3 = 2; k3 < 38; k3 += 2) {
        XLOAD(k3);
#pragma unroll
        for (int jp = 0; jp < 16; jp++)
            w0[jp] = f2_fma(m2[jp], w1[jp], w0[jp]);          // even: -2c*w1 + w0
        DOT_TAIL(w0, k3);
        XLOAD(k3 + 1);
#pragma unroll
        for (int jp = 0; jp < 16; jp++)
            w1[jp] = f2_fma(p2[jp], w0[jp], w1[jp]);          // odd: +2c*w0 + w1
        DOT_TAIL(w1, k3 + 1);
    }
    XLOAD(38);
#pragma unroll
    for (int jp = 0; jp < 16; jp++)
        w0[jp] = f2_fma(m2[jp], w1[jp], w0[jp]);
    DOT_TAIL(w0, 38);
#undef XLOAD
#undef DOT_TAIL
}

// ---------------------------------------------------------------------------
extern "C" void kernel_launch(void* const* d_in, const int* in_sizes, int n_in,
                              void* d_out, int out_size) {
    const float* vol = (const float*)d_in[0];
    const float* M   = (const float*)d_in[1];
    const float* P   = (const float*)d_in[2];
    float* out = (float*)d_out;

    static int attr_set = 0;
    if (!attr_set) {
        cudaFuncSetAttribute(k_main, cudaFuncAttributeMaxDynamicSharedMemorySize,
                             SM_FLOATS * 4);
        attr_set = 1;
    }
    const int nblk = (NPAIR + WPB - 1) / WPB;   // 139
    k_pre <<<4, 256>>>();
    k_main<<<nblk, TPB, SM_FLOATS * 4>>>(vol, M, P, out);
}

// round 17
// speedup vs baseline: 1.1109x; 1.1109x over previous
#include <cuda_runtime.h>

// Problem: volume [40,40,40,32] f32, M [32,32], P [32,32] -> Nk [59319,32]
//   b = (k1*39 + k2)*39 + k3
//   Nk[b,i] = sum_j x[b,j] * P[i,j] * cos(k1*a_ij) * cos(k2*a_ij) * cos(k3*a_ij)
//   a_ij = 2pi/(i*32+j+2),  x = (2x2x2 mean pool) @ M^T
//
// R17: two-kernel split, both shaped for their bottleneck.
//  k_xg:   254 blocks x 256 thr, 6 pairs/block: pool + matvec + sign fold
//          -> g_x. Blocks 0-3 also generate the cos table. High occupancy.
//  k_march: R15's measured-18.2us kernel verbatim: 139 blocks x 352 thr,
//          register-resident Chebyshev march over k3 (1 warp = 1 pair).
#define NP    39
#define NPAIR (39*39)     // 1521
#define PPB   6           // pairs per k_xg block
#define WPB   11          // pairs (warps) per k_march block
#define TPB   (WPB*32)    // 352
#define PI2F  6.2831853071795864769f

typedef unsigned long long ull;

__device__ float g_tab[39 * 1024];        // tab[k][j*32+i] = cos(k*2pi/(i*32+j+2))
__device__ float g_x[NPAIR * NP * 32];    // x'[pair][k3*32 + j], sign-folded

// ---- f32x2 packed math (sm_103a) ------------------------------------------
__device__ __forceinline__ ull f2_fma(ull a, ull b, ull c) {
    ull d; asm("fma.rn.f32x2 %0, %1, %2, %3;" : "=l"(d) : "l"(a), "l"(b), "l"(c)); return d;
}
__device__ __forceinline__ ull f2_add(ull a, ull b) {
    ull d; asm("add.rn.f32x2 %0, %1, %2;" : "=l"(d) : "l"(a), "l"(b)); return d;
}
__device__ __forceinline__ ull f2_pack2(float lo, float hi) {
    ull d; asm("mov.b64 %0, {%1, %2};" : "=l"(d) : "f"(lo), "f"(hi)); return d;
}
__device__ __forceinline__ float2 f2_unpack(ull v) {
    float2 r; asm("mov.b64 {%0, %1}, %2;" : "=f"(r.x), "=f"(r.y) : "l"(v)); return r;
}

// ---------------------------------------------------------------------------
// Kernel 1: x generation, 6 pairs per block. grid 254 x 256, 37.8 KB smem.
// Blocks 0-3 also build the cos table (k_xg itself never reads g_tab).
// ---------------------------------------------------------------------------
__global__ void __launch_bounds__(256) k_xg(
    const float* __restrict__ vol, const float* __restrict__ Mw)
{
    __shared__ float MT_s[1024];              // MT[l*32+j] = M[j][l]
    __shared__ float pooled[PPB * 1404];      // pooled[lp][k3*36 + ch]

    const int tid = threadIdx.x;
    const int p0  = blockIdx.x * PPB;

    // Table generation on the first 4 blocks.
    if (blockIdx.x < 4) {
        int t = blockIdx.x * 256 + tid;       // t = j*32 + i
        int i = t & 31, j = t >> 5;
        float a  = PI2F / (float)(i * 32 + j + 2);
        float c1 = cosf(a);
        float twoc = 2.0f * c1;
        float cm2 = 1.0f, cm1 = c1;
        g_tab[t]        = 1.0f;
        g_tab[1024 + t] = c1;
#pragma unroll
        for (int k = 2; k < 39; k++) {
            float ck = twoc * cm1 - cm2;
            g_tab[k * 1024 + t] = ck;
            cm2 = cm1; cm1 = ck;
        }
    }

    // Stage MT (transpose of M)
    for (int t = tid; t < 1024; t += 256)
        MT_s[t] = Mw[(t & 31) * 32 + (t >> 5)];

    // Pooling: job = (lp, k3, cq); 6*312 = 1872 jobs, 8 independent LDG.128
    for (int job = tid; job < PPB * 312; job += 256) {
        int lp  = job / 312;
        int rem = job - lp * 312;
        int k3  = rem >> 3;
        int cq  = rem & 7;
        int gp  = p0 + lp;
        if (gp >= NPAIR) continue;
        int k1 = gp / 39, k2 = gp - k1 * 39;
        const float* base = vol + (((k1 * 40) + k2) * 40 + k3) * 32 + cq * 4;
        float4 s = make_float4(0.f, 0.f, 0.f, 0.f);
#pragma unroll
        for (int dd = 0; dd < 2; dd++)
#pragma unroll
            for (int hh = 0; hh < 2; hh++)
#pragma unroll
                for (int ww = 0; ww < 2; ww++) {
                    float4 v = *(const float4*)(base + dd * 51200 + hh * 1280 + ww * 32);
                    s.x += v.x; s.y += v.y; s.z += v.z; s.w += v.w;
                }
        s.x *= 0.125f; s.y *= 0.125f; s.z *= 0.125f; s.w *= 0.125f;
        *(float4*)&pooled[lp * 1404 + k3 * 36 + cq * 4] = s;
    }
    __syncthreads();

    // Matvec + sign fold: x'[k3][j] = s_k3 * sum_l MT[l][j] * pooled[k3][l]
    for (int job = tid; job < PPB * 312; job += 256) {
        int lp  = job / 312;
        int rem = job - lp * 312;
        int k3  = rem >> 3;
        int jq  = rem & 7;
        int gp  = p0 + lp;
        if (gp >= NPAIR) continue;
        float a0 = 0.f, a1 = 0.f, a2 = 0.f, a3 = 0.f;
#pragma unroll
        for (int l = 0; l < 32; l++) {
            float p4 = pooled[lp * 1404 + k3 * 36 + l];
            float4 m4 = *(const float4*)&MT_s[l * 32 + jq * 4];
            a0 += p4 * m4.x; a1 += p4 * m4.y; a2 += p4 * m4.z; a3 += p4 * m4.w;
        }
        float sgn = (k3 & 2) ? -1.0f : 1.0f;                  // s_k: +,+,-,-
        *(float4*)&g_x[gp * 1248 + k3 * 32 + jq * 4] =
            make_float4(sgn * a0, sgn * a1, sgn * a2, sgn * a3);
    }
}

// ---------------------------------------------------------------------------
// Kernel 2: Chebyshev march (R15 verbatim, measured 18.2us).
// grid 139 x 352 threads, 59.1 KB static smem, 1 block/SM.
// ---------------------------------------------------------------------------
#define S_PT  0          // 1056   P^T padded [j*33 + i]
#define S_X   1056       // 11*1248 = 13728  x'[lp][k3*32+j]
#define SM_FLOATS 14784

__global__ void __launch_bounds__(TPB) k_march(
    const float* __restrict__ P, float* __restrict__ out)
{
    __shared__ float sm[SM_FLOATS];
    const int tid  = threadIdx.x;
    const int lane = tid & 31;
    const int wid  = tid >> 5;
    const int p0   = blockIdx.x * WPB;
    const int pair = p0 + wid;
    const bool valid = (pair < NPAIR);

    // -------- Stage P^T (padded) and x rows (coalesced LDG -> STS) --------
    for (int g = tid; g < 1024; g += TPB)
        sm[S_PT + (g & 31) * 33 + (g >> 5)] = P[g];           // PT[j][i] = P[i][j]

    {
        const float4* gx4 = (const float4*)g_x;
        float4*       sx4 = (float4*)(sm + S_X);
        const int base4 = p0 * 312;
        const int cap4  = NPAIR * 312;
        for (int idx = tid; idx < WPB * 312; idx += TPB) {
            int gi = base4 + idx;
            sx4[idx] = (gi < cap4) ? gx4[gi] : make_float4(0.f, 0.f, 0.f, 0.f);
        }
    }
    __syncthreads();

    if (!valid) return;                                       // no syncs after this

    // -------- Seeds (PT smem + g_tab rows) --------
    const int k1 = pair / 39, k2 = pair - (pair / 39) * 39;
    const float* t1r = g_tab + k1 * 1024;
    const float* t2r = g_tab + k2 * 1024;
    const float* cr  = g_tab + 1024;                          // k=1 row: cos(a)

    ull w0[16], w1[16], p2[16], m2[16];
#pragma unroll
    for (int jp = 0; jp < 16; jp++) {
        int t0 = (2 * jp) * 32 + lane, t1 = t0 + 32;
        float pa = sm[S_PT + (2 * jp) * 33 + lane];
        float pb = sm[S_PT + (2 * jp + 1) * 33 + lane];
        float a0 = pa * t1r[t0] * t2r[t0];                    // A[i, 2jp]
        float a1 = pb * t1r[t1] * t2r[t1];                    // A[i, 2jp+1]
        float c0 = cr[t0], c1 = cr[t1];
        w0[jp] = f2_pack2(a0, a1);                            // w_0 = A
        w1[jp] = f2_pack2(a0 * c0, a1 * c1);                  // w_1 = A*c
        p2[jp] = f2_pack2(2.0f * c0, 2.0f * c1);              // +2c
        m2[jp] = f2_pack2(-2.0f * c0, -2.0f * c1);            // -2c
    }

    // -------- March k3; x-row LDS hoisted ahead of recurrence --------
    const ulonglong2* xq = (const ulonglong2*)(sm + S_X + wid * 1248);
    float* outp = out + pair * (NP * 32) + lane;
    ulonglong2 xb[8];

#define XLOAD(K3) do { _Pragma("unroll")                                  \
    for (int q = 0; q < 8; q++) xb[q] = xq[(K3) * 8 + q]; } while (0)

#define DOT_TAIL(W, K3) do {                                              \
    ull a0 = 0, a1 = 0, a2 = 0, a3 = 0;                                   \
    _Pragma("unroll")                                                     \
    for (int q = 0; q < 8; q += 2) {                                      \
        a0 = f2_fma(W[2*q + 0], xb[q].x,     a0);                         \
        a1 = f2_fma(W[2*q + 1], xb[q].y,     a1);                         \
        a2 = f2_fma(W[2*q + 2], xb[q + 1].x, a2);                         \
        a3 = f2_fma(W[2*q + 3], xb[q + 1].y, a3);                         \
    }                                                                     \
    float2 fr = f2_unpack(f2_add(f2_add(a0, a1), f2_add(a2, a3)));        \
    outp[(K3) * 32] = fr.x + fr.y;                                        \
} while (0)

    XLOAD(0); DOT_TAIL(w0, 0);
    XLOAD(1); DOT_TAIL(w1, 1);

#pragma unroll 1
    for (int k3 = 2; k3 < 38; k3 += 2) {
        XLOAD(k3);
#pragma unroll
        for (int jp = 0; jp < 16; jp++)
            w0[jp] = f2_fma(m2[jp], w1[jp], w0[jp]);          // even: -2c*w1 + w0
        DOT_TAIL(w0, k3);
        XLOAD(k3 + 1);
#pragma unroll
        for (int jp = 0; jp < 16; jp++)
            w1[jp] = f2_fma(p2[jp], w0[jp], w1[jp]);          // odd: +2c*w0 + w1
        DOT_TAIL(w1, k3 + 1);
    }
    XLOAD(38);
#pragma unroll
    for (int jp = 0; jp < 16; jp++)
        w0[jp] = f2_fma(m2[jp], w1[jp], w0[jp]);
    DOT_TAIL(w0, 38);
#undef XLOAD
#undef DOT_TAIL
}

// ---------------------------------------------------------------------------
extern "C" void kernel_launch(void* const* d_in, const int* in_sizes, int n_in,
                              void* d_out, int out_size) {
    const float* vol = (const float*)d_in[0];
    const float* M   = (const float*)d_in[1];
    const float* P   = (const float*)d_in[2];
    float* out = (float*)d_out;

    const int xblk = (NPAIR + PPB - 1) / PPB;            // 254
    k_xg   <<<xblk, 256>>>(vol, M);
    k_march<<<(NPAIR + WPB - 1) / WPB, TPB>>>(P, out);   // 139
}